// round 14
// baseline (speedup 1.0000x reference)
#include <cuda_runtime.h>
#include <math_constants.h>
#include <stdint.h>

// Problem constants
#define BB 2
#define SS 2048
#define DD 1024
#define HH 16
#define HDIM 64
#define MROWS (BB * SS)      // 4096
#define NQKV (3 * DD)        // 3072

// Scratch (allocation-free rule: __device__ globals)
// k-pair permutation pi(j) = 2*(j&3) + (j>>2) applied within 8-groups of the
// contraction index on A-operand producers:
//   g_xr   : x with D-columns permuted
//   g_qkv  : Q,K thirds have HD-columns permuted; V third plain
//   g_attn : D-columns permuted (feeds outproj A)
__device__ float g_qkv[(size_t)MROWS * NQKV];
__device__ float g_attn[(size_t)MROWS * DD];
__device__ float g_xr[(size_t)MROWS * DD];
__device__ float g_wqkvr[(size_t)DD * NQKV];    // tf32-rounded w_qkv (plain)
__device__ float g_woutr[(size_t)DD * DD];      // tf32-rounded w_out (plain)

__device__ __forceinline__ uint32_t f2tf32(float f) {
    uint32_t u;
    asm("cvt.rna.tf32.f32 %0, %1;" : "=r"(u) : "f"(f));
    return u;
}

__device__ __forceinline__ void mma_tf32(float d[4],
                                         uint32_t a0, uint32_t a1, uint32_t a2, uint32_t a3,
                                         uint32_t b0, uint32_t b1) {
    asm volatile(
        "mma.sync.aligned.m16n8k8.row.col.f32.tf32.tf32.f32 "
        "{%0,%1,%2,%3}, {%4,%5,%6,%7}, {%8,%9}, {%0,%1,%2,%3};"
        : "+f"(d[0]), "+f"(d[1]), "+f"(d[2]), "+f"(d[3])
        : "r"(a0), "r"(a1), "r"(a2), "r"(a3), "r"(b0), "r"(b1));
}

__device__ __forceinline__ void cp16(uint32_t dst_smem, const void* src) {
    asm volatile("cp.async.cg.shared.global [%0], [%1], 16;"
                 :: "r"(dst_smem), "l"(src));
}
__device__ __forceinline__ void cp_commit() {
    asm volatile("cp.async.commit_group;" ::: "memory");
}
template <int N>
__device__ __forceinline__ void cp_wait_n() {
    asm volatile("cp.async.wait_group %0;" :: "n"(N) : "memory");
}

// ---- mbarrier helpers (sm_80-class ops; no arch-specific suffixes) ----
__device__ __forceinline__ uint32_t smem_u32(const void* p) {
    uint32_t a;
    asm("{ .reg .u64 t; cvta.to.shared.u64 t, %1; cvt.u32.u64 %0, t; }"
        : "=r"(a) : "l"(p));
    return a;
}
__device__ __forceinline__ void mbar_init(uint32_t mbar, uint32_t cnt) {
    asm volatile("mbarrier.init.shared.b64 [%0], %1;" :: "r"(mbar), "r"(cnt) : "memory");
}
__device__ __forceinline__ void mbar_arrive(uint32_t mbar) {
    asm volatile("{ .reg .b64 t; mbarrier.arrive.shared.b64 t, [%0]; }"
                 :: "r"(mbar) : "memory");
}
__device__ __forceinline__ void cp_async_mbar_arrive(uint32_t mbar) {
    asm volatile("cp.async.mbarrier.arrive.noinc.shared.b64 [%0];"
                 :: "r"(mbar) : "memory");
}
__device__ __forceinline__ void mbar_wait(uint32_t mbar, uint32_t parity) {
    asm volatile(
        "{\n\t"
        ".reg .pred P1;\n\t"
        "WAIT_%=:\n\t"
        "mbarrier.try_wait.parity.shared.b64 P1, [%0], %1;\n\t"
        "@!P1 bra WAIT_%=;\n\t"
        "}"
        :: "r"(mbar), "r"(parity) : "memory");
}

// ---------------------------------------------------------------------------
// Pre-round inputs to tf32. x additionally gets the k-pair permutation:
// per 8-group [j0..j7] -> [j0,j4,j1,j5,j2,j6,j3,j7].
// ---------------------------------------------------------------------------
__global__ __launch_bounds__(256)
void pre_round(const float4* __restrict__ x,
               const float4* __restrict__ wq,
               const float4* __restrict__ wo)
{
    const int NX8 = (MROWS * DD) / 8;       // 8-float granules of x
    const int NQ  = (DD * NQKV) / 4;
    const int NO  = (DD * DD) / 4;
    for (int i = blockIdx.x * blockDim.x + threadIdx.x;
         i < NX8 + NQ + NO; i += gridDim.x * blockDim.x) {
        if (i < NX8) {
            float4 lo = x[2 * i], hi = x[2 * i + 1];
            uint4 t0 = make_uint4(f2tf32(lo.x), f2tf32(hi.x), f2tf32(lo.y), f2tf32(hi.y));
            uint4 t1 = make_uint4(f2tf32(lo.z), f2tf32(hi.z), f2tf32(lo.w), f2tf32(hi.w));
            ((float4*)g_xr)[2 * i]     = *reinterpret_cast<float4*>(&t0);
            ((float4*)g_xr)[2 * i + 1] = *reinterpret_cast<float4*>(&t1);
        } else if (i < NX8 + NQ) {
            float4 v = wq[i - NX8];
            uint4 t = make_uint4(f2tf32(v.x), f2tf32(v.y), f2tf32(v.z), f2tf32(v.w));
            ((float4*)g_wqkvr)[i - NX8] = *reinterpret_cast<float4*>(&t);
        } else {
            float4 v = wo[i - NX8 - NQ];
            uint4 t = make_uint4(f2tf32(v.x), f2tf32(v.y), f2tf32(v.z), f2tf32(v.w));
            ((float4*)g_woutr)[i - NX8 - NQ] = *reinterpret_cast<float4*>(&t);
        }
    }
}

// ---------------------------------------------------------------------------
// TF32 tensor-core GEMM, 3-stage cp.async pipeline (unchanged R9 winner).
// ---------------------------------------------------------------------------
#define ASTR 40
#define ASZ (128 * ASTR)
#define BSZ (32 * 136)
#define STAGE (ASZ + BSZ)

template <int MODE>
__global__ __launch_bounds__(256, 2)
void mma_gemm(float* __restrict__ Cp)
{
    extern __shared__ uint32_t dynsmem[];
    constexpr int N_ = (MODE == 0) ? NQKV : DD;
    constexpr int K_ = DD;
    constexpr int NK = K_ / 32;            // 32

    const float* A  = (MODE == 0) ? (const float*)g_xr    : (const float*)g_attn;
    const float* Bm = (MODE == 0) ? (const float*)g_wqkvr : (const float*)g_woutr;
    float* C = (MODE == 0) ? (float*)g_qkv : Cp;

    const int tid  = threadIdx.x;
    const int warp = tid >> 5;
    const int lane = tid & 31;
    const int r = lane >> 2;
    const int c = lane & 3;

    const int bm = blockIdx.y * 128;
    const int bn = blockIdx.x * 128;
    const int wm = (warp >> 2) * 64;
    const int wn = (warp & 3) * 32;

    const uint32_t smem_base = (uint32_t)__cvta_generic_to_shared(dynsmem);

    float acc[4][4][4] = {};

    auto load_tiles = [&](int st, int k0) {
        uint32_t abase = smem_base + (uint32_t)(st * STAGE) * 4u;
        uint32_t bbase = abase + (uint32_t)ASZ * 4u;
        #pragma unroll
        for (int p = 0; p < 4; p++) {
            int f4 = tid + p * 256;
            int rr = f4 >> 3;
            int cc = (f4 & 7) << 2;
            cp16(abase + (uint32_t)(rr * ASTR + cc) * 4u,
                 A + (size_t)(bm + rr) * K_ + k0 + cc);
        }
        #pragma unroll
        for (int p = 0; p < 4; p++) {
            int f4 = tid + p * 256;
            int rr = f4 >> 5;
            int cc = (f4 & 31) << 2;
            cp16(bbase + (uint32_t)(rr * 136 + cc) * 4u,
                 Bm + (size_t)(k0 + rr) * N_ + bn + cc);
        }
        cp_commit();
    };

    load_tiles(0, 0);
    load_tiles(1, 32);

    int st = 0;
    for (int i = 0; i < NK; i++) {
        if (i + 1 < NK) cp_wait_n<1>();   // load(i) complete; load(i+1) in flight
        else            cp_wait_n<0>();
        __syncthreads();                  // compute(i-1) readers of buf st2 done
        if (i + 2 < NK) {
            int st2 = st + 2; if (st2 >= 3) st2 -= 3;
            load_tiles(st2, (i + 2) << 5);
        }

        const uint32_t* Asb = dynsmem + st * STAGE;
        const uint32_t* Bsb = Asb + ASZ;

        #pragma unroll
        for (int ks = 0; ks < 4; ks++) {
            const int kk = ks * 8;
            uint32_t af[4][4], bf[4][2];
            #pragma unroll
            for (int mi = 0; mi < 4; mi++) {
                int row = wm + mi * 16 + r;
                uint2 aa0 = *reinterpret_cast<const uint2*>(&Asb[row * ASTR + kk + 2 * c]);
                uint2 aa1 = *reinterpret_cast<const uint2*>(&Asb[(row + 8) * ASTR + kk + 2 * c]);
                af[mi][0] = aa0.x; af[mi][1] = aa1.x;
                af[mi][2] = aa0.y; af[mi][3] = aa1.y;
            }
            #pragma unroll
            for (int ni = 0; ni < 4; ni++) {
                int col = wn + ni * 8 + r;
                bf[ni][0] = Bsb[(kk + c) * 136 + col];
                bf[ni][1] = Bsb[(kk + c + 4) * 136 + col];
            }
            #pragma unroll
            for (int mi = 0; mi < 4; mi++)
                #pragma unroll
                for (int ni = 0; ni < 4; ni++)
                    mma_tf32(acc[mi][ni], af[mi][0], af[mi][1], af[mi][2], af[mi][3],
                             bf[ni][0], bf[ni][1]);
        }
        if (++st == 3) st = 0;
    }

    const int p0 = ((2 * c) & 3) * 2 + ((2 * c) >> 2);
    const int p1 = ((2 * c + 1) & 3) * 2 + ((2 * c + 1) >> 2);
    #pragma unroll
    for (int mi = 0; mi < 4; mi++) {
        int row0 = bm + wm + mi * 16 + r;
        #pragma unroll
        for (int ni = 0; ni < 4; ni++) {
            if (MODE == 0) {
                uint32_t v0 = f2tf32(acc[mi][ni][0]);
                uint32_t v1 = f2tf32(acc[mi][ni][1]);
                uint32_t v2 = f2tf32(acc[mi][ni][2]);
                uint32_t v3 = f2tf32(acc[mi][ni][3]);
                if (bn < 2 * DD) {     // Q or K third: permuted scatter
                    int gb = bn + wn + ni * 8;
                    uint32_t* c0 = (uint32_t*)(C + (size_t)row0 * N_ + gb);
                    uint32_t* c1 = (uint32_t*)(C + (size_t)(row0 + 8) * N_ + gb);
                    c0[p0] = v0;  c0[p1] = v1;
                    c1[p0] = v2;  c1[p1] = v3;
                } else {               // V third: plain
                    int col = bn + wn + ni * 8 + c * 2;
                    *reinterpret_cast<uint2*>(C + (size_t)row0 * N_ + col) = make_uint2(v0, v1);
                    *reinterpret_cast<uint2*>(C + (size_t)(row0 + 8) * N_ + col) = make_uint2(v2, v3);
                }
            } else {
                int col = bn + wn + ni * 8 + c * 2;
                *reinterpret_cast<float2*>(C + (size_t)row0 * N_ + col) =
                    make_float2(acc[mi][ni][0], acc[mi][ni][1]);
                *reinterpret_cast<float2*>(C + (size_t)(row0 + 8) * N_ + col) =
                    make_float2(acc[mi][ni][2], acc[mi][ni][3]);
            }
        }
    }
}

// ---------------------------------------------------------------------------
// Warp-specialized TF32 causal flash attention.
// 160 threads: warps 0-3 = consumers (16 q-rows each; math identical to R9),
// warp 4 = producer (all K/V cp.async loads).
// Sync: mbarriers only — NO __syncthreads in the key-tile loop.
//   full[b]  (count 32): producer cp.async-arrives after loading tile into buf b
//   empty[b] (count 128): consumers arrive after finishing tile in buf b
// Parity: buffer b's n-th use (n = kt>>1) waits parity n&1; producer waits
// empty parity (n-1)&1, skipping the first fill of each buffer (kt < 2).
// ---------------------------------------------------------------------------
#define KST 72
#define VST 72
#define KPSZ (64 * KST)
#define VSZ  (64 * VST)

__global__ __launch_bounds__(160, 3)
void attn_mma(void)
{
    extern __shared__ uint32_t dynsmem[];
    __shared__ uint64_t s_mbar[4];   // full0, full1, empty0, empty1

    const int tid = threadIdx.x;
    const int w  = tid >> 5;             // 0..4
    const int l  = tid & 31;
    const int lr = l >> 2;
    const int lc = l & 3;
    const int qt = gridDim.x - 1 - blockIdx.x;   // long blocks first
    const int h  = blockIdx.y;
    const int b  = blockIdx.z;
    const int ldq = NQKV;

    const float* qb  = g_qkv + ((size_t)b * SS + (size_t)qt * 64) * ldq + h * HDIM;
    const float* kb0 = g_qkv + (size_t)b * SS * ldq + DD + h * HDIM;
    const float* vb0 = g_qkv + (size_t)b * SS * ldq + 2 * DD + h * HDIM;

    const uint32_t smem_base = (uint32_t)__cvta_generic_to_shared(dynsmem);
    const uint32_t mb = smem_u32(s_mbar);
    const uint32_t full0  = mb,      full1  = mb + 8;
    const uint32_t empty0 = mb + 16, empty1 = mb + 24;

    if (tid == 0) {
        mbar_init(full0, 32);  mbar_init(full1, 32);
        mbar_init(empty0, 128); mbar_init(empty1, 128);
    }
    __syncthreads();   // one-time: mbarriers visible to all warps

    if (w == 4) {
        // ---------------- producer warp ----------------
        for (int kt = 0; kt <= qt; kt++) {
            const int bidx = kt & 1;
            const int n = kt >> 1;
            if (kt >= 2) mbar_wait(bidx ? empty1 : empty0, (uint32_t)((n - 1) & 1));
            const float* kb = kb0 + (size_t)kt * 64 * ldq;
            const float* vb = vb0 + (size_t)kt * 64 * ldq;
            uint32_t kbase = smem_base + (uint32_t)(bidx * KPSZ) * 4u;
            uint32_t vbase = smem_base + (uint32_t)(2 * KPSZ + bidx * VSZ) * 4u;
            #pragma unroll 8
            for (int p = 0; p < 32; p++) {           // K: 1024 float4
                int f4 = l + p * 32;
                int r  = f4 >> 4;
                int c4 = (f4 & 15) << 2;
                cp16(kbase + (uint32_t)(r * KST + c4) * 4u, kb + (size_t)r * ldq + c4);
            }
            #pragma unroll 8
            for (int p = 0; p < 32; p++) {           // V: 1024 float4, sigma rows
                int f4 = l + p * 32;
                int r  = f4 >> 4;
                int c4 = (f4 & 15) << 2;
                int vr = (r & 56) | (((r & 1) << 2) | ((r & 7) >> 1));
                cp16(vbase + (uint32_t)(vr * VST + c4) * 4u, vb + (size_t)r * ldq + c4);
            }
            cp_async_mbar_arrive(bidx ? full1 : full0);
        }
        return;
    }

    // ---------------- consumer warps 0-3 ----------------
    // Q fragments: permuted pair (2lc,2lc+1) == original (d=8ks+lc, d=8ks+lc+4)
    uint32_t qf[8][4];
    {
        const float* q0 = qb + (size_t)(w * 16 + lr) * ldq;
        const float* q1 = q0 + (size_t)8 * ldq;
        #pragma unroll
        for (int ks = 0; ks < 8; ks++) {
            float2 f0 = *reinterpret_cast<const float2*>(q0 + ks * 8 + 2 * lc);
            float2 f1 = *reinterpret_cast<const float2*>(q1 + ks * 8 + 2 * lc);
            qf[ks][0] = f2tf32(f0.x * 0.125f);
            qf[ks][1] = f2tf32(f1.x * 0.125f);
            qf[ks][2] = f2tf32(f0.y * 0.125f);
            qf[ks][3] = f2tf32(f1.y * 0.125f);
        }
    }

    float o[8][4] = {};
    float mA = -CUDART_INF_F, mB = -CUDART_INF_F;
    float lA = 0.f, lB = 0.f;

    const int rowA = w * 16 + lr;
    const int rowB = rowA + 8;

    for (int kt = 0; kt <= qt; kt++) {
        const int bidx = kt & 1;
        const int n = kt >> 1;
        mbar_wait(bidx ? full1 : full0, (uint32_t)(n & 1));   // K/V(kt) ready

        const uint32_t* KPb = dynsmem + bidx * KPSZ;
        const uint32_t* Vsb = dynsmem + 2 * KPSZ + bidx * VSZ;

        // ---- S = Q @ K^T (K HD-permuted -> LDS.64 b-fragments) ----
        float s[8][4] = {};
        #pragma unroll
        for (int ks = 0; ks < 8; ks++) {
            const int kk = ks * 8;
            #pragma unroll
            for (int ni = 0; ni < 8; ni++) {
                uint2 bb = *reinterpret_cast<const uint2*>(
                    &KPb[(ni * 8 + lr) * KST + kk + 2 * lc]);
                mma_tf32(s[ni], qf[ks][0], qf[ks][1], qf[ks][2], qf[ks][3], bb.x, bb.y);
            }
        }

        if (kt == qt) {
            #pragma unroll
            for (int ni = 0; ni < 8; ni++) {
                int c0 = ni * 8 + 2 * lc;
                int c1 = c0 + 1;
                if (c0 > rowA) s[ni][0] = -CUDART_INF_F;
                if (c1 > rowA) s[ni][1] = -CUDART_INF_F;
                if (c0 > rowB) s[ni][2] = -CUDART_INF_F;
                if (c1 > rowB) s[ni][3] = -CUDART_INF_F;
            }
        }

        // ---- online softmax (fp32), P stays in registers ----
        float mxA = -CUDART_INF_F, mxB = -CUDART_INF_F;
        #pragma unroll
        for (int ni = 0; ni < 8; ni++) {
            mxA = fmaxf(mxA, fmaxf(s[ni][0], s[ni][1]));
            mxB = fmaxf(mxB, fmaxf(s[ni][2], s[ni][3]));
        }
        #pragma unroll
        for (int off = 1; off <= 2; off <<= 1) {
            mxA = fmaxf(mxA, __shfl_xor_sync(0xffffffffu, mxA, off));
            mxB = fmaxf(mxB, __shfl_xor_sync(0xffffffffu, mxB, off));
        }
        const float mnA = fmaxf(mA, mxA);
        const float mnB = fmaxf(mB, mxB);
        const float cA = __expf(mA - mnA);
        const float cB = __expf(mB - mnB);
        mA = mnA;  mB = mnB;
        #pragma unroll
        for (int ni = 0; ni < 8; ni++) {
            o[ni][0] *= cA;  o[ni][1] *= cA;
            o[ni][2] *= cB;  o[ni][3] *= cB;
        }

        // ---- fused exp + PV: for each key group kg, s[kg] IS the A-frag ----
        float rsA = 0.f, rsB = 0.f;
        #pragma unroll
        for (int kg = 0; kg < 8; kg++) {
            const int kk = kg * 8;
            float p0 = __expf(s[kg][0] - mnA);
            float p1 = __expf(s[kg][1] - mnA);
            float p2 = __expf(s[kg][2] - mnB);
            float p3 = __expf(s[kg][3] - mnB);
            rsA += p0 + p1;
            rsB += p2 + p3;
            uint32_t a0 = f2tf32(p0);
            uint32_t a1 = f2tf32(p2);
            uint32_t a2 = f2tf32(p1);
            uint32_t a3 = f2tf32(p3);
            #pragma unroll
            for (int ni = 0; ni < 8; ni++) {
                uint32_t b0 = Vsb[(kk + lc) * VST + ni * 8 + lr];
                uint32_t b1 = Vsb[(kk + lc + 4) * VST + ni * 8 + lr];
                mma_tf32(o[ni], a0, a1, a2, a3, b0, b1);
            }
        }
        #pragma unroll
        for (int off = 1; off <= 2; off <<= 1) {
            rsA += __shfl_xor_sync(0xffffffffu, rsA, off);
            rsB += __shfl_xor_sync(0xffffffffu, rsB, off);
        }
        lA = lA * cA + rsA;
        lB = lB * cB + rsB;

        mbar_arrive(bidx ? empty1 : empty0);   // release buf bidx to producer
    }

    // Epilogue: normalize, tf32-round, write with k-pair permutation
    const float iA = 1.0f / lA;
    const float iB = 1.0f / lB;
    const int p0 = ((2 * lc) & 3) * 2 + ((2 * lc) >> 2);
    const int p1 = ((2 * lc + 1) & 3) * 2 + ((2 * lc + 1) >> 2);
    float* obA = g_attn + ((size_t)b * SS + (size_t)qt * 64 + rowA) * DD + h * HDIM;
    float* obB = obA + (size_t)8 * DD;
    #pragma unroll
    for (int ni = 0; ni < 8; ni++) {
        uint32_t* dA = (uint32_t*)(obA + ni * 8);
        uint32_t* dB = (uint32_t*)(obB + ni * 8);
        dA[p0] = f2tf32(o[ni][0] * iA);
        dA[p1] = f2tf32(o[ni][1] * iA);
        dB[p0] = f2tf32(o[ni][2] * iB);
        dB[p1] = f2tf32(o[ni][3] * iB);
    }
}

// ---------------------------------------------------------------------------
extern "C" void kernel_launch(void* const* d_in, const int* in_sizes, int n_in,
                              void* d_out, int out_size)
{
    const float* x    = (const float*)d_in[0];  // (2,2048,1024)
    const float* wqkv = (const float*)d_in[1];  // (1024,3072)
    const float* wout = (const float*)d_in[2];  // (1024,1024)
    float* out = (float*)d_out;                 // (2,2048,1024)

    const int GEMM_SMEM = (3 * STAGE) * 4;           // 113664
    const int ATTN_SMEM = (2 * KPSZ + 2 * VSZ) * 4;  // 73728
    cudaFuncSetAttribute(mma_gemm<0>, cudaFuncAttributeMaxDynamicSharedMemorySize, GEMM_SMEM);
    cudaFuncSetAttribute(mma_gemm<1>, cudaFuncAttributeMaxDynamicSharedMemorySize, GEMM_SMEM);
    cudaFuncSetAttribute(attn_mma,    cudaFuncAttributeMaxDynamicSharedMemorySize, ATTN_SMEM);

    // 0) Round to tf32 once (x also gets the k-pair permutation)
    pre_round<<<2048, 256>>>((const float4*)x, (const float4*)wqkv, (const float4*)wout);

    // 1) QKV projection -> g_qkv
    mma_gemm<0><<<dim3(NQKV / 128, MROWS / 128), 256, GEMM_SMEM>>>(nullptr);

    // 2) Causal attention -> g_attn  [warp-specialized producer/consumer]
    attn_mma<<<dim3(SS / 64, HH, BB), 160, ATTN_SMEM>>>();

    // 3) Output projection -> d_out (fp32)
    mma_gemm<1><<<dim3(DD / 128, MROWS / 128), 256, GEMM_SMEM>>>(out);
}

// round 15
// speedup vs baseline: 1.0327x; 1.0327x over previous
#include <cuda_runtime.h>
#include <math_constants.h>
#include <stdint.h>

// Problem constants
#define BB 2
#define SS 2048
#define DD 1024
#define HH 16
#define HDIM 64
#define MROWS (BB * SS)      // 4096
#define NQKV (3 * DD)        // 3072

// Scratch (allocation-free rule: __device__ globals)
// k-pair permutation pi(j) = 2*(j&3) + (j>>2) applied within 8-groups of the
// contraction index on A-operand producers:
//   g_xr   : x with D-columns permuted
//   g_qkv  : Q,K thirds have HD-columns permuted; V third plain
//   g_attn : D-columns permuted (feeds outproj A)
__device__ float g_qkv[(size_t)MROWS * NQKV];
__device__ float g_attn[(size_t)MROWS * DD];
__device__ float g_xr[(size_t)MROWS * DD];
__device__ float g_wqkvr[(size_t)DD * NQKV];    // tf32-rounded w_qkv (plain)
__device__ float g_woutr[(size_t)DD * DD];      // tf32-rounded w_out (plain)

__device__ __forceinline__ uint32_t f2tf32(float f) {
    uint32_t u;
    asm("cvt.rna.tf32.f32 %0, %1;" : "=r"(u) : "f"(f));
    return u;
}

__device__ __forceinline__ float ex2(float x) {
    float r;
    asm("ex2.approx.f32 %0, %1;" : "=f"(r) : "f"(x));
    return r;
}

__device__ __forceinline__ void mma_tf32(float d[4],
                                         uint32_t a0, uint32_t a1, uint32_t a2, uint32_t a3,
                                         uint32_t b0, uint32_t b1) {
    asm volatile(
        "mma.sync.aligned.m16n8k8.row.col.f32.tf32.tf32.f32 "
        "{%0,%1,%2,%3}, {%4,%5,%6,%7}, {%8,%9}, {%0,%1,%2,%3};"
        : "+f"(d[0]), "+f"(d[1]), "+f"(d[2]), "+f"(d[3])
        : "r"(a0), "r"(a1), "r"(a2), "r"(a3), "r"(b0), "r"(b1));
}

__device__ __forceinline__ void cp16(uint32_t dst_smem, const void* src) {
    asm volatile("cp.async.cg.shared.global [%0], [%1], 16;"
                 :: "r"(dst_smem), "l"(src));
}
__device__ __forceinline__ void cp_commit() {
    asm volatile("cp.async.commit_group;" ::: "memory");
}
template <int N>
__device__ __forceinline__ void cp_wait_n() {
    asm volatile("cp.async.wait_group %0;" :: "n"(N) : "memory");
}
__device__ __forceinline__ void cp_wait(int pending) {
    if (pending) asm volatile("cp.async.wait_group 1;" ::: "memory");
    else         asm volatile("cp.async.wait_group 0;" ::: "memory");
}

// ---------------------------------------------------------------------------
// Pre-round inputs to tf32. x additionally gets the k-pair permutation:
// per 8-group [j0..j7] -> [j0,j4,j1,j5,j2,j6,j3,j7].
// ---------------------------------------------------------------------------
__global__ __launch_bounds__(256)
void pre_round(const float4* __restrict__ x,
               const float4* __restrict__ wq,
               const float4* __restrict__ wo)
{
    const int NX8 = (MROWS * DD) / 8;       // 8-float granules of x
    const int NQ  = (DD * NQKV) / 4;
    const int NO  = (DD * DD) / 4;
    for (int i = blockIdx.x * blockDim.x + threadIdx.x;
         i < NX8 + NQ + NO; i += gridDim.x * blockDim.x) {
        if (i < NX8) {
            float4 lo = x[2 * i], hi = x[2 * i + 1];
            uint4 t0 = make_uint4(f2tf32(lo.x), f2tf32(hi.x), f2tf32(lo.y), f2tf32(hi.y));
            uint4 t1 = make_uint4(f2tf32(lo.z), f2tf32(hi.z), f2tf32(lo.w), f2tf32(hi.w));
            ((float4*)g_xr)[2 * i]     = *reinterpret_cast<float4*>(&t0);
            ((float4*)g_xr)[2 * i + 1] = *reinterpret_cast<float4*>(&t1);
        } else if (i < NX8 + NQ) {
            float4 v = wq[i - NX8];
            uint4 t = make_uint4(f2tf32(v.x), f2tf32(v.y), f2tf32(v.z), f2tf32(v.w));
            ((float4*)g_wqkvr)[i - NX8] = *reinterpret_cast<float4*>(&t);
        } else {
            float4 v = wo[i - NX8 - NQ];
            uint4 t = make_uint4(f2tf32(v.x), f2tf32(v.y), f2tf32(v.z), f2tf32(v.w));
            ((float4*)g_woutr)[i - NX8 - NQ] = *reinterpret_cast<float4*>(&t);
        }
    }
}

// ---------------------------------------------------------------------------
// TF32 tensor-core GEMM, 3-stage cp.async pipeline (unchanged R9/R12 winner).
// ---------------------------------------------------------------------------
#define ASTR 40
#define ASZ (128 * ASTR)
#define BSZ (32 * 136)
#define STAGE (ASZ + BSZ)

template <int MODE>
__global__ __launch_bounds__(256, 2)
void mma_gemm(float* __restrict__ Cp)
{
    extern __shared__ uint32_t dynsmem[];
    constexpr int N_ = (MODE == 0) ? NQKV : DD;
    constexpr int K_ = DD;
    constexpr int NK = K_ / 32;            // 32

    const float* A  = (MODE == 0) ? (const float*)g_xr    : (const float*)g_attn;
    const float* Bm = (MODE == 0) ? (const float*)g_wqkvr : (const float*)g_woutr;
    float* C = (MODE == 0) ? (float*)g_qkv : Cp;

    const int tid  = threadIdx.x;
    const int warp = tid >> 5;
    const int lane = tid & 31;
    const int r = lane >> 2;
    const int c = lane & 3;

    const int bm = blockIdx.y * 128;
    const int bn = blockIdx.x * 128;
    const int wm = (warp >> 2) * 64;
    const int wn = (warp & 3) * 32;

    const uint32_t smem_base = (uint32_t)__cvta_generic_to_shared(dynsmem);

    float acc[4][4][4] = {};

    auto load_tiles = [&](int st, int k0) {
        uint32_t abase = smem_base + (uint32_t)(st * STAGE) * 4u;
        uint32_t bbase = abase + (uint32_t)ASZ * 4u;
        #pragma unroll
        for (int p = 0; p < 4; p++) {
            int f4 = tid + p * 256;
            int rr = f4 >> 3;
            int cc = (f4 & 7) << 2;
            cp16(abase + (uint32_t)(rr * ASTR + cc) * 4u,
                 A + (size_t)(bm + rr) * K_ + k0 + cc);
        }
        #pragma unroll
        for (int p = 0; p < 4; p++) {
            int f4 = tid + p * 256;
            int rr = f4 >> 5;
            int cc = (f4 & 31) << 2;
            cp16(bbase + (uint32_t)(rr * 136 + cc) * 4u,
                 Bm + (size_t)(k0 + rr) * N_ + bn + cc);
        }
        cp_commit();
    };

    load_tiles(0, 0);
    load_tiles(1, 32);

    int st = 0;
    for (int i = 0; i < NK; i++) {
        if (i + 1 < NK) cp_wait_n<1>();   // load(i) complete; load(i+1) in flight
        else            cp_wait_n<0>();
        __syncthreads();                  // compute(i-1) readers of buf st2 done
        if (i + 2 < NK) {
            int st2 = st + 2; if (st2 >= 3) st2 -= 3;
            load_tiles(st2, (i + 2) << 5);
        }

        const uint32_t* Asb = dynsmem + st * STAGE;
        const uint32_t* Bsb = Asb + ASZ;

        #pragma unroll
        for (int ks = 0; ks < 4; ks++) {
            const int kk = ks * 8;
            uint32_t af[4][4], bf[4][2];
            #pragma unroll
            for (int mi = 0; mi < 4; mi++) {
                int row = wm + mi * 16 + r;
                uint2 aa0 = *reinterpret_cast<const uint2*>(&Asb[row * ASTR + kk + 2 * c]);
                uint2 aa1 = *reinterpret_cast<const uint2*>(&Asb[(row + 8) * ASTR + kk + 2 * c]);
                af[mi][0] = aa0.x; af[mi][1] = aa1.x;
                af[mi][2] = aa0.y; af[mi][3] = aa1.y;
            }
            #pragma unroll
            for (int ni = 0; ni < 4; ni++) {
                int col = wn + ni * 8 + r;
                bf[ni][0] = Bsb[(kk + c) * 136 + col];
                bf[ni][1] = Bsb[(kk + c + 4) * 136 + col];
            }
            #pragma unroll
            for (int mi = 0; mi < 4; mi++)
                #pragma unroll
                for (int ni = 0; ni < 4; ni++)
                    mma_tf32(acc[mi][ni], af[mi][0], af[mi][1], af[mi][2], af[mi][3],
                             bf[ni][0], bf[ni][1]);
        }
        if (++st == 3) st = 0;
    }

    const int p0 = ((2 * c) & 3) * 2 + ((2 * c) >> 2);
    const int p1 = ((2 * c + 1) & 3) * 2 + ((2 * c + 1) >> 2);
    #pragma unroll
    for (int mi = 0; mi < 4; mi++) {
        int row0 = bm + wm + mi * 16 + r;
        #pragma unroll
        for (int ni = 0; ni < 4; ni++) {
            if (MODE == 0) {
                uint32_t v0 = f2tf32(acc[mi][ni][0]);
                uint32_t v1 = f2tf32(acc[mi][ni][1]);
                uint32_t v2 = f2tf32(acc[mi][ni][2]);
                uint32_t v3 = f2tf32(acc[mi][ni][3]);
                if (bn < 2 * DD) {     // Q or K third: permuted scatter
                    int gb = bn + wn + ni * 8;
                    uint32_t* c0 = (uint32_t*)(C + (size_t)row0 * N_ + gb);
                    uint32_t* c1 = (uint32_t*)(C + (size_t)(row0 + 8) * N_ + gb);
                    c0[p0] = v0;  c0[p1] = v1;
                    c1[p0] = v2;  c1[p1] = v3;
                } else {               // V third: plain
                    int col = bn + wn + ni * 8 + c * 2;
                    *reinterpret_cast<uint2*>(C + (size_t)row0 * N_ + col) = make_uint2(v0, v1);
                    *reinterpret_cast<uint2*>(C + (size_t)(row0 + 8) * N_ + col) = make_uint2(v2, v3);
                }
            } else {
                int col = bn + wn + ni * 8 + c * 2;
                *reinterpret_cast<float2*>(C + (size_t)row0 * N_ + col) =
                    make_float2(acc[mi][ni][0], acc[mi][ni][1]);
                *reinterpret_cast<float2*>(C + (size_t)(row0 + 8) * N_ + col) =
                    make_float2(acc[mi][ni][2], acc[mi][ni][3]);
            }
        }
    }
}

// ---------------------------------------------------------------------------
// TF32 tensor-core causal flash attention — register-resident P (R9 structure)
// with a shortened softmax critical path:
//   * Q pre-scaled by 0.125*log2(e): scores live in log2 domain, every exp is
//     a single ex2.approx (no FMUL on the exp chain). Softmax is base-invariant.
//   * Row-sum l kept as PER-THREAD partials (l = l*c + rs_thread is linear and
//     c is quad-uniform); quad-reduced once in the epilogue. Only the row-max
//     keeps its per-tile shuffle reduction.
// Sync structure, V sigma-permutation, buffers: identical to the champion.
// ---------------------------------------------------------------------------
#define KST 72
#define VST 72
#define KPSZ (64 * KST)
#define VSZ  (64 * VST)

__global__ __launch_bounds__(128, 3)
void attn_mma(void)
{
    extern __shared__ uint32_t dynsmem[];

    const int tid = threadIdx.x;
    const int w  = tid >> 5;
    const int l  = tid & 31;
    const int lr = l >> 2;
    const int lc = l & 3;
    const int qt = gridDim.x - 1 - blockIdx.x;   // long blocks first
    const int h  = blockIdx.y;
    const int b  = blockIdx.z;
    const int ldq = NQKV;

    const float* qb  = g_qkv + ((size_t)b * SS + (size_t)qt * 64) * ldq + h * HDIM;
    const float* kb0 = g_qkv + (size_t)b * SS * ldq + DD + h * HDIM;
    const float* vb0 = g_qkv + (size_t)b * SS * ldq + 2 * DD + h * HDIM;

    const uint32_t smem_base = (uint32_t)__cvta_generic_to_shared(dynsmem);

    auto load_kv = [&](int st, int kt) {
        const float* kb = kb0 + (size_t)kt * 64 * ldq;
        const float* vb = vb0 + (size_t)kt * 64 * ldq;
        uint32_t kbase = smem_base + (uint32_t)(st * KPSZ) * 4u;
        uint32_t vbase = smem_base + (uint32_t)(2 * KPSZ + st * VSZ) * 4u;
        #pragma unroll
        for (int p = 0; p < 8; p++) {
            int f4 = tid + p * 128;
            int r  = f4 >> 4;
            int c4 = (f4 & 15) << 2;
            cp16(kbase + (uint32_t)(r * KST + c4) * 4u, kb + (size_t)r * ldq + c4);
            // V: permuted key-row slot  sigma(r&7) = 4*(r&1) + ((r&7)>>1)
            int vr = (r & 56) | (((r & 1) << 2) | ((r & 7) >> 1));
            cp16(vbase + (uint32_t)(vr * VST + c4) * 4u, vb + (size_t)r * ldq + c4);
        }
        cp_commit();
    };

    // Q fragments: permuted pair (2lc,2lc+1) == original (d=8ks+lc, d=8ks+lc+4)
    // Pre-scaled by 0.125 * log2(e) so scores are in the log2 domain.
    const float QSC = 0.125f * 1.4426950408889634f;
    uint32_t qf[8][4];
    {
        const float* q0 = qb + (size_t)(w * 16 + lr) * ldq;
        const float* q1 = q0 + (size_t)8 * ldq;
        #pragma unroll
        for (int ks = 0; ks < 8; ks++) {
            float2 f0 = *reinterpret_cast<const float2*>(q0 + ks * 8 + 2 * lc);
            float2 f1 = *reinterpret_cast<const float2*>(q1 + ks * 8 + 2 * lc);
            qf[ks][0] = f2tf32(f0.x * QSC);
            qf[ks][1] = f2tf32(f1.x * QSC);
            qf[ks][2] = f2tf32(f0.y * QSC);
            qf[ks][3] = f2tf32(f1.y * QSC);
        }
    }

    load_kv(0, 0);

    float o[8][4] = {};
    float mA = -CUDART_INF_F, mB = -CUDART_INF_F;
    float lA = 0.f, lB = 0.f;          // PER-THREAD partial row sums

    const int rowA = w * 16 + lr;
    const int rowB = rowA + 8;

    for (int kt = 0; kt <= qt; kt++) {
        const int cur = kt & 1;
        __syncthreads();                  // buf cur^1 readers (kt-1) done
        const int has_next = (kt < qt);
        if (has_next) load_kv(cur ^ 1, kt + 1);
        cp_wait(has_next);                // K/V(kt) arrived
        __syncthreads();                  // visible to all warps

        const uint32_t* KPb = dynsmem + cur * KPSZ;
        const uint32_t* Vsb = dynsmem + 2 * KPSZ + cur * VSZ;

        // ---- S = Q @ K^T (K HD-permuted -> LDS.64 b-fragments) ----
        float s[8][4] = {};
        #pragma unroll
        for (int ks = 0; ks < 8; ks++) {
            const int kk = ks * 8;
            #pragma unroll
            for (int ni = 0; ni < 8; ni++) {
                uint2 bb = *reinterpret_cast<const uint2*>(
                    &KPb[(ni * 8 + lr) * KST + kk + 2 * lc]);
                mma_tf32(s[ni], qf[ks][0], qf[ks][1], qf[ks][2], qf[ks][3], bb.x, bb.y);
            }
        }

        if (kt == qt) {
            #pragma unroll
            for (int ni = 0; ni < 8; ni++) {
                int c0 = ni * 8 + 2 * lc;
                int c1 = c0 + 1;
                if (c0 > rowA) s[ni][0] = -CUDART_INF_F;
                if (c1 > rowA) s[ni][1] = -CUDART_INF_F;
                if (c0 > rowB) s[ni][2] = -CUDART_INF_F;
                if (c1 > rowB) s[ni][3] = -CUDART_INF_F;
            }
        }

        // ---- online softmax (log2 domain), P stays in registers ----
        float mxA = -CUDART_INF_F, mxB = -CUDART_INF_F;
        #pragma unroll
        for (int ni = 0; ni < 8; ni++) {
            mxA = fmaxf(mxA, fmaxf(s[ni][0], s[ni][1]));
            mxB = fmaxf(mxB, fmaxf(s[ni][2], s[ni][3]));
        }
        #pragma unroll
        for (int off = 1; off <= 2; off <<= 1) {
            mxA = fmaxf(mxA, __shfl_xor_sync(0xffffffffu, mxA, off));
            mxB = fmaxf(mxB, __shfl_xor_sync(0xffffffffu, mxB, off));
        }
        const float mnA = fmaxf(mA, mxA);
        const float mnB = fmaxf(mB, mxB);
        const float cA = ex2(mA - mnA);
        const float cB = ex2(mB - mnB);
        mA = mnA;  mB = mnB;
        #pragma unroll
        for (int ni = 0; ni < 8; ni++) {
            o[ni][0] *= cA;  o[ni][1] *= cA;
            o[ni][2] *= cB;  o[ni][3] *= cB;
        }

        // ---- fused ex2 + PV: for each key group kg, s[kg] IS the A-frag ----
        float rsA = 0.f, rsB = 0.f;
        #pragma unroll
        for (int kg = 0; kg < 8; kg++) {
            const int kk = kg * 8;
            float p0 = ex2(s[kg][0] - mnA);
            float p1 = ex2(s[kg][1] - mnA);
            float p2 = ex2(s[kg][2] - mnB);
            float p3 = ex2(s[kg][3] - mnB);
            rsA += p0 + p1;
            rsB += p2 + p3;
            uint32_t a0 = f2tf32(p0);
            uint32_t a1 = f2tf32(p2);
            uint32_t a2 = f2tf32(p1);
            uint32_t a3 = f2tf32(p3);
            #pragma unroll
            for (int ni = 0; ni < 8; ni++) {
                uint32_t b0 = Vsb[(kk + lc) * VST + ni * 8 + lr];
                uint32_t b1 = Vsb[(kk + lc + 4) * VST + ni * 8 + lr];
                mma_tf32(o[ni], a0, a1, a2, a3, b0, b1);
            }
        }
        // per-thread partial update; quad reduction deferred to epilogue
        lA = lA * cA + rsA;
        lB = lB * cB + rsB;
    }

    // Epilogue: quad-reduce partial sums, normalize, tf32-round, write permuted
    #pragma unroll
    for (int off = 1; off <= 2; off <<= 1) {
        lA += __shfl_xor_sync(0xffffffffu, lA, off);
        lB += __shfl_xor_sync(0xffffffffu, lB, off);
    }
    const float iA = 1.0f / lA;
    const float iB = 1.0f / lB;
    const int p0 = ((2 * lc) & 3) * 2 + ((2 * lc) >> 2);
    const int p1 = ((2 * lc + 1) & 3) * 2 + ((2 * lc + 1) >> 2);
    float* obA = g_attn + ((size_t)b * SS + (size_t)qt * 64 + rowA) * DD + h * HDIM;
    float* obB = obA + (size_t)8 * DD;
    #pragma unroll
    for (int ni = 0; ni < 8; ni++) {
        uint32_t* dA = (uint32_t*)(obA + ni * 8);
        uint32_t* dB = (uint32_t*)(obB + ni * 8);
        dA[p0] = f2tf32(o[ni][0] * iA);
        dA[p1] = f2tf32(o[ni][1] * iA);
        dB[p0] = f2tf32(o[ni][2] * iB);
        dB[p1] = f2tf32(o[ni][3] * iB);
    }
}

// ---------------------------------------------------------------------------
extern "C" void kernel_launch(void* const* d_in, const int* in_sizes, int n_in,
                              void* d_out, int out_size)
{
    const float* x    = (const float*)d_in[0];  // (2,2048,1024)
    const float* wqkv = (const float*)d_in[1];  // (1024,3072)
    const float* wout = (const float*)d_in[2];  // (1024,1024)
    float* out = (float*)d_out;                 // (2,2048,1024)

    const int GEMM_SMEM = (3 * STAGE) * 4;           // 113664
    const int ATTN_SMEM = (2 * KPSZ + 2 * VSZ) * 4;  // 73728
    cudaFuncSetAttribute(mma_gemm<0>, cudaFuncAttributeMaxDynamicSharedMemorySize, GEMM_SMEM);
    cudaFuncSetAttribute(mma_gemm<1>, cudaFuncAttributeMaxDynamicSharedMemorySize, GEMM_SMEM);
    cudaFuncSetAttribute(attn_mma,    cudaFuncAttributeMaxDynamicSharedMemorySize, ATTN_SMEM);

    // 0) Round to tf32 once (x also gets the k-pair permutation)
    pre_round<<<2048, 256>>>((const float4*)x, (const float4*)wqkv, (const float4*)wout);

    // 1) QKV projection -> g_qkv
    mma_gemm<0><<<dim3(NQKV / 128, MROWS / 128), 256, GEMM_SMEM>>>(nullptr);

    // 2) Causal attention -> g_attn  [register-P, log2-domain softmax]
    attn_mma<<<dim3(SS / 64, HH, BB), 128, ATTN_SMEM>>>();

    // 3) Output projection -> d_out (fp32)
    mma_gemm<1><<<dim3(DD / 128, MROWS / 128), 256, GEMM_SMEM>>>(out);
}